// round 6
// baseline (speedup 1.0000x reference)
#include <cuda_runtime.h>
#include <math.h>

#define T_TOK   2048
#define H_DIM   128
#define H4_DIM  512
#define N_NODES 256
#define TB      8    // token chunk per pass

// Scratch (allocation-free per harness rules)
__device__ int   g_count[N_NODES];
__device__ int   g_tokens[N_NODES * T_TOK];
__device__ float g_h[T_TOK * H4_DIM];   // 4 MB intermediate (L2-resident)

__global__ void zero_counts_kernel() {
    g_count[threadIdx.x] = 0;
}

__global__ void build_lists_kernel(const int* __restrict__ node_ind) {
    int t = blockIdx.x * blockDim.x + threadIdx.x;
    if (t < T_TOK) {
        int n = node_ind[t];
        int pos = atomicAdd(&g_count[n], 1);
        g_tokens[n * T_TOK + pos] = t;
    }
}

__device__ __forceinline__ float gelu_exact(float v) {
    return 0.5f * v * (1.0f + erff(v * 0.70710678118654752f));
}

// ---- Layer 1: grid = N_NODES*4 CTAs. CTA (n,q) owns rows [q*128,(q+1)*128)
// of W1[n] (64 KB), loaded into registers ONCE, reused over all tokens of n.
// NO occupancy clamp: 128-reg budget so wv[]/acc[] stay in registers.
__global__ __launch_bounds__(512)
void layer1_kernel(const float* __restrict__ x,
                   const float* __restrict__ W1,
                   const float* __restrict__ b1) {
    __shared__ float xs[TB][H_DIM];
    __shared__ int   stoks[TB];

    const int b = blockIdx.x;
    const int n = b >> 2;
    const int q = b & 3;

    const int tid  = threadIdx.x;
    const int w    = tid >> 5;
    const int lane = tid & 31;
    const int g    = lane >> 3;   // row group 0..3
    const int c    = lane & 7;    // chunk 0..7 (16 floats per lane per row)

    const float* W1c = W1 + (size_t)n * H4_DIM * H_DIM + (size_t)q * 128 * H_DIM;
    const float* b1c = b1 + n * H4_DIM + q * 128;

    // Load weights first (independent of count) so LDGs overlap the count load.
    float4 wv[2][4];
    #pragma unroll
    for (int it = 0; it < 2; it++) {
        const int rr = it * 64 + w * 4 + g;
        const float4* wr = (const float4*)(W1c + (size_t)rr * H_DIM);
        #pragma unroll
        for (int j = 0; j < 4; j++) wv[it][j] = wr[j * 8 + c];
    }

    const int nt_total = g_count[n];

    for (int base = 0; base < nt_total; base += TB) {
        const int nt = min(TB, nt_total - base);

        __syncthreads();
        if (tid < nt) stoks[tid] = g_tokens[n * T_TOK + base + tid];
        __syncthreads();
        if (tid < nt * 32) {
            int tk = tid >> 5;
            int l4 = tid & 31;
            ((float4*)xs[tk])[l4] =
                ((const float4*)(x + (size_t)stoks[tk] * H_DIM))[l4];
        }
        __syncthreads();

        #pragma unroll
        for (int it = 0; it < 2; it++) {
            const int rr = it * 64 + w * 4 + g;
            float acc[TB];
            #pragma unroll
            for (int t = 0; t < TB; t++) {
                acc[t] = 0.f;
                if (t < nt) {
                    #pragma unroll
                    for (int j = 0; j < 4; j++) {
                        float4 xv = ((const float4*)xs[t])[j * 8 + c];
                        acc[t] += wv[it][j].x * xv.x + wv[it][j].y * xv.y
                                + wv[it][j].z * xv.z + wv[it][j].w * xv.w;
                    }
                }
            }
            #pragma unroll
            for (int t = 0; t < TB; t++) {
                if (t < nt) {
                    float v = acc[t];
                    v += __shfl_xor_sync(0xffffffffu, v, 4);
                    v += __shfl_xor_sync(0xffffffffu, v, 2);
                    v += __shfl_xor_sync(0xffffffffu, v, 1);
                    if (c == 0)
                        g_h[(size_t)stoks[t] * H4_DIM + q * 128 + rr] =
                            gelu_exact(v + b1c[rr]);
                }
            }
        }
    }
}

// ---- Layer 2: grid = N_NODES*4 CTAs. CTA (n,q) owns rows [q*32,(q+1)*32)
// of W2[n] (64 KB), in registers once. Warp w: rows w + it*16; dot over 32 lanes.
__global__ __launch_bounds__(512)
void layer2_kernel(const float* __restrict__ W2,
                   const float* __restrict__ b2,
                   float* __restrict__ out) {
    __shared__ float hs[TB][H4_DIM];   // 16 KB
    __shared__ int   stoks[TB];

    const int b = blockIdx.x;
    const int n = b >> 2;
    const int q = b & 3;

    const int tid  = threadIdx.x;
    const int w    = tid >> 5;
    const int lane = tid & 31;

    const float* W2c = W2 + (size_t)n * H_DIM * H4_DIM + (size_t)q * 32 * H4_DIM;
    const float* b2c = b2 + n * H_DIM + q * 32;

    // Load weights first: 2 rows x 4 float4 = 32 regs
    float4 wv[2][4];
    #pragma unroll
    for (int it = 0; it < 2; it++) {
        const int rr = w + it * 16;
        const float4* wr = (const float4*)(W2c + (size_t)rr * H4_DIM);
        #pragma unroll
        for (int j = 0; j < 4; j++) wv[it][j] = wr[j * 32 + lane];
    }

    const int nt_total = g_count[n];

    for (int base = 0; base < nt_total; base += TB) {
        const int nt = min(TB, nt_total - base);

        __syncthreads();
        if (tid < nt) stoks[tid] = g_tokens[n * T_TOK + base + tid];
        __syncthreads();
        // Stage h rows: nt*128 float4; 512 threads -> up to 2 each
        #pragma unroll
        for (int k = 0; k < 2; k++) {
            int idx = tid + k * 512;
            int tk = idx >> 7;        // token 0..7
            int l4 = idx & 127;       // float4 within row
            if (tk < nt)
                ((float4*)hs[tk])[l4] =
                    ((const float4*)(g_h + (size_t)stoks[tk] * H4_DIM))[l4];
        }
        __syncthreads();

        #pragma unroll
        for (int it = 0; it < 2; it++) {
            const int rr = w + it * 16;
            float acc[TB];
            #pragma unroll
            for (int t = 0; t < TB; t++) {
                acc[t] = 0.f;
                if (t < nt) {
                    #pragma unroll
                    for (int j = 0; j < 4; j++) {
                        float4 hv = ((const float4*)hs[t])[j * 32 + lane];
                        acc[t] += wv[it][j].x * hv.x + wv[it][j].y * hv.y
                                + wv[it][j].z * hv.z + wv[it][j].w * hv.w;
                    }
                }
            }
            #pragma unroll
            for (int t = 0; t < TB; t++) {
                if (t < nt) {
                    float v = acc[t];
                    #pragma unroll
                    for (int s = 16; s > 0; s >>= 1)
                        v += __shfl_xor_sync(0xffffffffu, v, s);
                    if (lane == 0)
                        out[(size_t)stoks[t] * H_DIM + q * 32 + rr] = v + b2c[rr];
                }
            }
        }
    }
}

extern "C" void kernel_launch(void* const* d_in, const int* in_sizes, int n_in,
                              void* d_out, int out_size) {
    const float* x        = (const float*)d_in[0];
    const int*   node_ind = (const int*)  d_in[1];
    const float* W1       = (const float*)d_in[2];
    const float* b1       = (const float*)d_in[3];
    const float* W2       = (const float*)d_in[4];
    const float* b2       = (const float*)d_in[5];
    float*       out      = (float*)d_out;

    zero_counts_kernel<<<1, N_NODES>>>();
    build_lists_kernel<<<(T_TOK + 255) / 256, 256>>>(node_ind);
    layer1_kernel<<<N_NODES * 4, 512>>>(x, W1, b1);
    layer2_kernel<<<N_NODES * 4, 512>>>(W2, b2, out);
}